// round 1
// baseline (speedup 1.0000x reference)
#include <cuda_runtime.h>
#include <math.h>

#define BB 1024
#define NN 128
#define KK 4
#define MTOT (BB*NN)   // 131072

// ---------------- scratch (device globals: allocation-free) ----------------
__device__ float g_out1[MTOT*64];
__device__ float g_out2[MTOT*128];
__device__ float g_out3[MTOT*256];
__device__ float g_U[MTOT*192];
__device__ float g_V[MTOT*192];
__device__ int   g_idx[MTOT*KK];
__device__ float g_hcat[(size_t)MTOT*464];   // K-padded concat (453 -> 464)
__device__ float g_h1[(size_t)MTOT*512];     // N-padded (453 -> 512)
__device__ float g_h2[(size_t)MTOT*256];     // N-padded (226 -> 256)
__device__ float g_W1p[464*512];
__device__ float g_b1p[512];
__device__ float g_W2p[464*256];
__device__ float g_b2p[256];
__device__ float g_W3p[256*2];

__device__ __forceinline__ float eluf(float x) { return x > 0.f ? x : expm1f(x); }

// ---------------- pad/copy weights into zero-padded buffers ----------------
__global__ void pad_copy_kernel(float* __restrict__ dst, const float* __restrict__ src,
                                int sr, int sc, int dr, int dc) {
    int tot = dr * dc;
    for (int i = blockIdx.x * blockDim.x + threadIdx.x; i < tot; i += gridDim.x * blockDim.x) {
        int r = i / dc, c = i % dc;
        dst[i] = (r < sr && c < sc) ? src[r * sc + c] : 0.f;
    }
}

// ---------------- KNN: block per batch, thread per point ----------------
template<int C>
__global__ void __launch_bounds__(128) knn_kernel(const float* __restrict__ x,
                                                  int* __restrict__ out_idx) {
    extern __shared__ float sm[];
    float* sx = sm;            // [128][C]
    float* sn = sm + NN * C;   // [128]
    int b = blockIdx.x, t = threadIdx.x;
    const float* xb = x + (size_t)b * NN * C;
    for (int i = t; i < NN * C; i += 128) sx[i] = xb[i];
    __syncthreads();
    float nrm = 0.f;
    float rx[C];
    #pragma unroll
    for (int c = 0; c < C; c++) { rx[c] = sx[t * C + c]; nrm += rx[c] * rx[c]; }
    sn[t] = nrm;
    __syncthreads();

    float bd0 = 3e38f, bd1 = 3e38f, bd2 = 3e38f, bd3 = 3e38f;
    int   bi0 = 0, bi1 = 0, bi2 = 0, bi3 = 0;
    for (int j = 0; j < NN; j++) {
        float dot = 0.f;
        if (C % 4 == 0) {
            #pragma unroll
            for (int c = 0; c < C; c += 4) {
                float4 v = *reinterpret_cast<const float4*>(&sx[j * C + c]);
                dot += rx[c] * v.x + rx[c+1] * v.y + rx[c+2] * v.z + rx[c+3] * v.w;
            }
        } else {
            #pragma unroll
            for (int c = 0; c < C; c++) dot += rx[c] * sx[j * C + c];
        }
        float d = nrm + sn[j] - 2.f * dot;       // same formula as reference
        if (j == t) d += 1e9f;                   // eye * 1e9
        if (d < bd3) {
            if (d < bd0)      { bd3=bd2;bi3=bi2; bd2=bd1;bi2=bi1; bd1=bd0;bi1=bi0; bd0=d;bi0=j; }
            else if (d < bd1) { bd3=bd2;bi3=bi2; bd2=bd1;bi2=bi1; bd1=d;bi1=j; }
            else if (d < bd2) { bd3=bd2;bi3=bi2; bd2=d;bi2=j; }
            else              { bd3=d;bi3=j; }
        }
    }
    int* o = out_idx + ((size_t)b * NN + t) * KK;
    o[0] = bi0; o[1] = bi1; o[2] = bi2; o[3] = bi3;
}

// ---------------- EdgeConv stage 1: U = X@W1b ; V = X@W1a - U + b1 ----------------
// w1: [2C][H] row-major. Block per batch, 256 threads (tx16 x ty16), 8x4 microtile.
template<int C, int H>
__global__ void __launch_bounds__(256) stage1_kernel(const float* __restrict__ x,
                                                     const float* __restrict__ w1,
                                                     const float* __restrict__ b1,
                                                     float* __restrict__ U,
                                                     float* __restrict__ V) {
    const int XS = 132;
    extern __shared__ float sm[];
    float* XT = sm;                  // [C][132]  (XT[c][p])
    float* Ba = sm + C * XS;         // [16][64]
    float* Bb = Ba + 16 * 64;        // [16][64]
    int b = blockIdx.x;
    int tid = threadIdx.x;
    int tx = tid & 15, ty = tid >> 4;
    const float* xb = x + (size_t)b * NN * C;
    for (int i = tid; i < NN * C; i += 256) {
        int p = i / C, c = i % C;
        XT[c * XS + p] = xb[i];
    }
    __syncthreads();

    const int NBT = (H + 63) / 64;
    for (int nb = 0; nb < NBT; nb++) {
        float au[8][4], aw[8][4];
        #pragma unroll
        for (int r = 0; r < 8; r++)
            #pragma unroll
            for (int c = 0; c < 4; c++) { au[r][c] = 0.f; aw[r][c] = 0.f; }

        for (int c0 = 0; c0 < C; c0 += 16) {
            int kc = (C - c0 < 16) ? (C - c0) : 16;
            __syncthreads();
            for (int li = tid; li < 16 * 64; li += 256) {
                int kk = li >> 6, n = li & 63;
                int h = nb * 64 + n;
                float va = 0.f, vb = 0.f;
                if (kk < kc && h < H) {
                    va = w1[(size_t)(c0 + kk) * H + h];
                    vb = w1[(size_t)(C + c0 + kk) * H + h];
                }
                Ba[kk * 64 + n] = va;
                Bb[kk * 64 + n] = vb;
            }
            __syncthreads();
            for (int kk = 0; kk < kc; kk++) {
                float4 a0 = *reinterpret_cast<float4*>(&XT[(c0 + kk) * XS + ty * 8]);
                float4 a1 = *reinterpret_cast<float4*>(&XT[(c0 + kk) * XS + ty * 8 + 4]);
                float4 va = *reinterpret_cast<float4*>(&Ba[kk * 64 + tx * 4]);
                float4 vb = *reinterpret_cast<float4*>(&Bb[kk * 64 + tx * 4]);
                float a[8]  = {a0.x, a0.y, a0.z, a0.w, a1.x, a1.y, a1.z, a1.w};
                float wa[4] = {va.x, va.y, va.z, va.w};
                float wb[4] = {vb.x, vb.y, vb.z, vb.w};
                #pragma unroll
                for (int r = 0; r < 8; r++)
                    #pragma unroll
                    for (int c = 0; c < 4; c++) {
                        au[r][c] = fmaf(a[r], wb[c], au[r][c]);
                        aw[r][c] = fmaf(a[r], wa[c], aw[r][c]);
                    }
            }
        }
        #pragma unroll
        for (int r = 0; r < 8; r++) {
            int p = ty * 8 + r;
            size_t base = ((size_t)b * NN + p) * H;
            #pragma unroll
            for (int c = 0; c < 4; c++) {
                int h = nb * 64 + tx * 4 + c;
                if (h < H) {
                    float u = au[r][c];
                    U[base + h] = u;
                    V[base + h] = aw[r][c] - u + b1[h];
                }
            }
        }
    }
}

// ---------------- EdgeConv stage 2: out[p] = mean_k elu(elu(V[p]+U[j]) @ W2 + b2) ----------------
// Grid (B, 4): 32 points (128 edges) per block. w2: [H][COUT].
template<int H, int COUT>
__global__ void __launch_bounds__(256) stage2_kernel(const float* __restrict__ U,
                                                     const float* __restrict__ V,
                                                     const int* __restrict__ idx,
                                                     const float* __restrict__ w2,
                                                     const float* __restrict__ b2,
                                                     float* __restrict__ out) {
    const int ES = 132;
    extern __shared__ float sm[];
    float* M1 = sm;              // [H][132]  (M1[h][e])
    float* Bs = sm + H * ES;     // [16][64]
    int b = blockIdx.x, pt = blockIdx.y;
    int tid = threadIdx.x;
    int tx = tid & 15, ty = tid >> 4;
    int p0 = pt * 32;

    { // phase A: build edge features (post first ELU), transposed
        int e = tid & 127, s = tid >> 7;
        int pl = e >> 2, kk = e & 3;
        int p = p0 + pl;
        int j = idx[((size_t)b * NN + p) * KK + kk];
        const float* vp = V + ((size_t)b * NN + p) * H;
        const float* up = U + ((size_t)b * NN + j) * H;
        int h0 = s * (H / 2), h1 = h0 + H / 2;
        for (int h = h0; h < h1; h++)
            M1[h * ES + e] = eluf(vp[h] + up[h]);
    }
    __syncthreads();

    const int NBT = COUT / 64;
    for (int nb = 0; nb < NBT; nb++) {
        float acc[8][4];
        #pragma unroll
        for (int r = 0; r < 8; r++)
            #pragma unroll
            for (int c = 0; c < 4; c++) acc[r][c] = 0.f;

        for (int k0 = 0; k0 < H; k0 += 16) {
            __syncthreads();
            { // load Bs [16][64], one float4 per thread
                int kk = tid >> 4, nq = tid & 15;
                *reinterpret_cast<float4*>(&Bs[kk * 64 + nq * 4]) =
                    *reinterpret_cast<const float4*>(&w2[(size_t)(k0 + kk) * COUT + nb * 64 + nq * 4]);
            }
            __syncthreads();
            #pragma unroll
            for (int kk = 0; kk < 16; kk++) {
                float4 a0 = *reinterpret_cast<float4*>(&M1[(k0 + kk) * ES + ty * 8]);
                float4 a1 = *reinterpret_cast<float4*>(&M1[(k0 + kk) * ES + ty * 8 + 4]);
                float4 b4 = *reinterpret_cast<float4*>(&Bs[kk * 64 + tx * 4]);
                float a[8]  = {a0.x, a0.y, a0.z, a0.w, a1.x, a1.y, a1.z, a1.w};
                float wv[4] = {b4.x, b4.y, b4.z, b4.w};
                #pragma unroll
                for (int r = 0; r < 8; r++)
                    #pragma unroll
                    for (int c = 0; c < 4; c++)
                        acc[r][c] = fmaf(a[r], wv[c], acc[r][c]);
            }
        }
        // epilogue: + b2, elu, mean over 4 edges (rows ty*8..+7 = points ty*2, ty*2+1)
        #pragma unroll
        for (int q = 0; q < 2; q++) {
            int p = p0 + ty * 2 + q;
            #pragma unroll
            for (int c = 0; c < 4; c++) {
                int o = nb * 64 + tx * 4 + c;
                float bias = b2[o];
                float s = 0.f;
                #pragma unroll
                for (int r = 0; r < 4; r++) s += eluf(acc[q * 4 + r][c] + bias);
                out[((size_t)b * NN + p) * COUT + o] = 0.25f * s;
            }
        }
    }
}

// ---------------- concat [features | out1 | out2 | out3 | zeros] -> g_hcat [M][464] ----------------
__global__ void concat_kernel(const float* __restrict__ feats) {
    size_t total = (size_t)MTOT * 464;
    for (size_t i = (size_t)blockIdx.x * blockDim.x + threadIdx.x; i < total;
         i += (size_t)gridDim.x * blockDim.x) {
        size_t m = i / 464;
        int c = (int)(i % 464);
        float v;
        if (c < 5)        v = feats[m * 5 + c];
        else if (c < 69)  v = g_out1[m * 64 + (c - 5)];
        else if (c < 197) v = g_out2[m * 128 + (c - 69)];
        else if (c < 453) v = g_out3[m * 256 + (c - 197)];
        else              v = 0.f;
        g_hcat[i] = v;
    }
}

// ---------------- generic GEMM + bias (+elu): C[M][ldc] = act(A[M][lda] @ Bm[K][ldb] + bias) ----------------
// BM=128, BN=64, BK=16. Grid (M/128, N/64). All dims padded -> no guards.
__global__ void __launch_bounds__(256) gemm_kernel(const float* __restrict__ A, int lda,
                                                   const float* __restrict__ Bm, int ldb,
                                                   const float* __restrict__ bias,
                                                   float* __restrict__ Cm, int ldc,
                                                   int Kdim, int do_elu) {
    __shared__ float As[16][132];
    __shared__ float Bs[16][64];
    int tid = threadIdx.x;
    int tx = tid & 15, ty = tid >> 4;
    size_t m0 = (size_t)blockIdx.x * 128;
    int n0 = blockIdx.y * 64;

    float acc[8][4];
    #pragma unroll
    for (int r = 0; r < 8; r++)
        #pragma unroll
        for (int c = 0; c < 4; c++) acc[r][c] = 0.f;

    for (int k0 = 0; k0 < Kdim; k0 += 16) {
        __syncthreads();
        for (int li = tid; li < 512; li += 256) {     // A tile 128x16, float4, store transposed
            int m = li >> 2, kq = li & 3;
            float4 v = *reinterpret_cast<const float4*>(&A[(m0 + m) * lda + k0 + kq * 4]);
            As[kq * 4 + 0][m] = v.x; As[kq * 4 + 1][m] = v.y;
            As[kq * 4 + 2][m] = v.z; As[kq * 4 + 3][m] = v.w;
        }
        {
            int kk = tid >> 4, nq = tid & 15;          // B tile 16x64, one float4 per thread
            *reinterpret_cast<float4*>(&Bs[kk][nq * 4]) =
                *reinterpret_cast<const float4*>(&Bm[(size_t)(k0 + kk) * ldb + n0 + nq * 4]);
        }
        __syncthreads();
        #pragma unroll
        for (int kk = 0; kk < 16; kk++) {
            float4 a0 = *reinterpret_cast<float4*>(&As[kk][ty * 8]);
            float4 a1 = *reinterpret_cast<float4*>(&As[kk][ty * 8 + 4]);
            float4 b4 = *reinterpret_cast<float4*>(&Bs[kk][tx * 4]);
            float a[8]  = {a0.x, a0.y, a0.z, a0.w, a1.x, a1.y, a1.z, a1.w};
            float wv[4] = {b4.x, b4.y, b4.z, b4.w};
            #pragma unroll
            for (int r = 0; r < 8; r++)
                #pragma unroll
                for (int c = 0; c < 4; c++)
                    acc[r][c] = fmaf(a[r], wv[c], acc[r][c]);
        }
    }
    #pragma unroll
    for (int r = 0; r < 8; r++) {
        size_t m = m0 + ty * 8 + r;
        #pragma unroll
        for (int c = 0; c < 4; c++) {
            int n = n0 + tx * 4 + c;
            float v = acc[r][c] + bias[n];
            if (do_elu) v = eluf(v);
            Cm[m * ldc + n] = v;
        }
    }
}

// ---------------- final tiny GEMM: out[m][0..1] = h2[m] @ W3p + b3 ----------------
__global__ void final_kernel(const float* __restrict__ b3, float* __restrict__ out) {
    int warp = (blockIdx.x * blockDim.x + threadIdx.x) >> 5;
    int lane = threadIdx.x & 31;
    if (warp >= MTOT) return;
    const float* row = g_h2 + (size_t)warp * 256;
    float a0 = 0.f, a1 = 0.f;
    for (int k = lane; k < 256; k += 32) {
        float v = row[k];
        a0 = fmaf(v, g_W3p[k * 2 + 0], a0);
        a1 = fmaf(v, g_W3p[k * 2 + 1], a1);
    }
    #pragma unroll
    for (int off = 16; off; off >>= 1) {
        a0 += __shfl_down_sync(0xFFFFFFFFu, a0, off);
        a1 += __shfl_down_sync(0xFFFFFFFFu, a1, off);
    }
    if (lane == 0) {
        out[(size_t)warp * 2 + 0] = a0 + b3[0];
        out[(size_t)warp * 2 + 1] = a1 + b3[1];
    }
}

// ---------------- launch ----------------
extern "C" void kernel_launch(void* const* d_in, const int* in_sizes, int n_in,
                              void* d_out, int out_size) {
    const float* coords = (const float*)d_in[0];
    const float* feats  = (const float*)d_in[1];
    const float* c1w1 = (const float*)d_in[2];  const float* c1b1 = (const float*)d_in[3];
    const float* c1w2 = (const float*)d_in[4];  const float* c1b2 = (const float*)d_in[5];
    const float* c2w1 = (const float*)d_in[6];  const float* c2b1 = (const float*)d_in[7];
    const float* c2w2 = (const float*)d_in[8];  const float* c2b2 = (const float*)d_in[9];
    const float* c3w1 = (const float*)d_in[10]; const float* c3b1 = (const float*)d_in[11];
    const float* c3w2 = (const float*)d_in[12]; const float* c3b2 = (const float*)d_in[13];
    const float* ow1  = (const float*)d_in[14]; const float* ob1  = (const float*)d_in[15];
    const float* ow2  = (const float*)d_in[16]; const float* ob2  = (const float*)d_in[17];
    const float* ow3  = (const float*)d_in[18]; const float* ob3  = (const float*)d_in[19];
    float* out = (float*)d_out;

    float *out1p, *out2p, *out3p, *Up, *Vp, *hcatp, *h1p, *h2p;
    float *W1pp, *b1pp, *W2pp, *b2pp, *W3pp;
    int* idxp;
    cudaGetSymbolAddress((void**)&out1p, g_out1);
    cudaGetSymbolAddress((void**)&out2p, g_out2);
    cudaGetSymbolAddress((void**)&out3p, g_out3);
    cudaGetSymbolAddress((void**)&Up,    g_U);
    cudaGetSymbolAddress((void**)&Vp,    g_V);
    cudaGetSymbolAddress((void**)&idxp,  g_idx);
    cudaGetSymbolAddress((void**)&hcatp, g_hcat);
    cudaGetSymbolAddress((void**)&h1p,   g_h1);
    cudaGetSymbolAddress((void**)&h2p,   g_h2);
    cudaGetSymbolAddress((void**)&W1pp,  g_W1p);
    cudaGetSymbolAddress((void**)&b1pp,  g_b1p);
    cudaGetSymbolAddress((void**)&W2pp,  g_W2p);
    cudaGetSymbolAddress((void**)&b2pp,  g_b2p);
    cudaGetSymbolAddress((void**)&W3pp,  g_W3p);

    // dynamic smem sizes
    const int sm_knn2   = (NN * 2 + NN) * 4;
    const int sm_knn64  = (NN * 64 + NN) * 4;
    const int sm_knn128 = (NN * 128 + NN) * 4;
    const int sm_s1_a = (5 * 132 + 2 * 16 * 64) * 4;
    const int sm_s1_b = (64 * 132 + 2 * 16 * 64) * 4;
    const int sm_s1_c = (128 * 132 + 2 * 16 * 64) * 4;
    const int sm_s2_a = (32 * 132 + 16 * 64) * 4;
    const int sm_s2_b = (96 * 132 + 16 * 64) * 4;
    const int sm_s2_c = (192 * 132 + 16 * 64) * 4;

    cudaFuncSetAttribute(knn_kernel<128>,          cudaFuncAttributeMaxDynamicSharedMemorySize, sm_knn128);
    cudaFuncSetAttribute(stage1_kernel<128, 192>,  cudaFuncAttributeMaxDynamicSharedMemorySize, sm_s1_c);
    cudaFuncSetAttribute(stage2_kernel<96, 128>,   cudaFuncAttributeMaxDynamicSharedMemorySize, sm_s2_b);
    cudaFuncSetAttribute(stage2_kernel<192, 256>,  cudaFuncAttributeMaxDynamicSharedMemorySize, sm_s2_c);

    // pad weights for the head GEMMs
    pad_copy_kernel<<<512, 256>>>(W1pp, ow1, 453, 453, 464, 512);
    pad_copy_kernel<<<2, 256>>>(b1pp, ob1, 1, 453, 1, 512);
    pad_copy_kernel<<<256, 256>>>(W2pp, ow2, 453, 226, 464, 256);
    pad_copy_kernel<<<1, 256>>>(b2pp, ob2, 1, 226, 1, 256);
    pad_copy_kernel<<<2, 256>>>(W3pp, ow3, 226, 2, 256, 2);

    // edgeconv 1
    knn_kernel<2><<<BB, 128, sm_knn2>>>(coords, idxp);
    stage1_kernel<5, 32><<<BB, 256, sm_s1_a>>>(feats, c1w1, c1b1, Up, Vp);
    stage2_kernel<32, 64><<<dim3(BB, 4), 256, sm_s2_a>>>(Up, Vp, idxp, c1w2, c1b2, out1p);
    // edgeconv 2
    knn_kernel<64><<<BB, 128, sm_knn64>>>(out1p, idxp);
    stage1_kernel<64, 96><<<BB, 256, sm_s1_b>>>(out1p, c2w1, c2b1, Up, Vp);
    stage2_kernel<96, 128><<<dim3(BB, 4), 256, sm_s2_b>>>(Up, Vp, idxp, c2w2, c2b2, out2p);
    // edgeconv 3
    knn_kernel<128><<<BB, 128, sm_knn128>>>(out2p, idxp);
    stage1_kernel<128, 192><<<BB, 256, sm_s1_c>>>(out2p, c3w1, c3b1, Up, Vp);
    stage2_kernel<192, 256><<<dim3(BB, 4), 256, sm_s2_c>>>(Up, Vp, idxp, c3w2, c3b2, out3p);
    // head
    concat_kernel<<<8192, 256>>>(feats);
    gemm_kernel<<<dim3(MTOT / 128, 8), 256>>>(hcatp, 464, W1pp, 512, b1pp, h1p, 512, 464, 1);
    gemm_kernel<<<dim3(MTOT / 128, 4), 256>>>(h1p, 512, W2pp, 256, b2pp, h2p, 256, 464, 1);
    final_kernel<<<MTOT / 8, 256>>>(ob3, out);
}

// round 3
// speedup vs baseline: 1.3107x; 1.3107x over previous
#include <cuda_runtime.h>
#include <cuda_bf16.h>
#include <math.h>
#include <stdint.h>

#define BB 1024
#define NN 128
#define KK 4
#define MTOT (BB*NN)   // 131072
#define KP 512         // padded K for head GEMMs

// ---------------- scratch (device globals: allocation-free) ----------------
__device__ float g_out1[MTOT*64];
__device__ float g_out2[MTOT*128];
__device__ float g_out3[MTOT*256];
__device__ float g_U[MTOT*192];
__device__ float g_V[MTOT*192];
__device__ int   g_idx[MTOT*KK];
__device__ float g_h2[(size_t)MTOT*256];     // N-padded (226 -> 256)
__device__ float g_b1p[512];
__device__ float g_b2p[256];
__device__ float g_W3p[256*2];

// bf16 split operands for tensor-core head GEMMs (16B aligned)
__device__ __align__(16) __nv_bfloat16 g_A1h[(size_t)MTOT*KP];
__device__ __align__(16) __nv_bfloat16 g_A1l[(size_t)MTOT*KP];
__device__ __align__(16) __nv_bfloat16 g_h1h[(size_t)MTOT*KP];
__device__ __align__(16) __nv_bfloat16 g_h1l[(size_t)MTOT*KP];
__device__ __align__(16) __nv_bfloat16 g_Bt1h[512*KP];
__device__ __align__(16) __nv_bfloat16 g_Bt1l[512*KP];
__device__ __align__(16) __nv_bfloat16 g_Bt2h[256*KP];
__device__ __align__(16) __nv_bfloat16 g_Bt2l[256*KP];

__device__ __forceinline__ float eluf(float x) { return x > 0.f ? x : expm1f(x); }

__device__ __forceinline__ uint32_t smem_u32(const void* p) {
    uint32_t a;
    asm("{ .reg .u64 t; cvta.to.shared.u64 t, %1; cvt.u32.u64 %0, t; }" : "=r"(a) : "l"(p));
    return a;
}
__device__ __forceinline__ void cp16(uint32_t dst, const void* src) {
    asm volatile("cp.async.cg.shared.global [%0], [%1], 16;" :: "r"(dst), "l"(src));
}
#define CP_COMMIT() asm volatile("cp.async.commit_group;" ::: "memory")
#define CP_WAIT(n)  asm volatile("cp.async.wait_group %0;" :: "n"(n) : "memory")

#define LDSM_X4(r0, r1, r2, r3, addr) \
    asm volatile("ldmatrix.sync.aligned.m8n8.x4.shared.b16 {%0,%1,%2,%3}, [%4];" \
        : "=r"(r0), "=r"(r1), "=r"(r2), "=r"(r3) : "r"(addr))
#define LDSM_X2(r0, r1, addr) \
    asm volatile("ldmatrix.sync.aligned.m8n8.x2.shared.b16 {%0,%1}, [%2];" \
        : "=r"(r0), "=r"(r1) : "r"(addr))

#define MMA16816(d, a0, a1, a2, a3, b0, b1) \
    asm volatile("mma.sync.aligned.m16n8k16.row.col.f32.bf16.bf16.f32 " \
        "{%0,%1,%2,%3}, {%4,%5,%6,%7}, {%8,%9}, {%0,%1,%2,%3};" \
        : "+f"((d)[0]), "+f"((d)[1]), "+f"((d)[2]), "+f"((d)[3]) \
        : "r"(a0), "r"(a1), "r"(a2), "r"(a3), "r"(b0), "r"(b1))

// ---------------- pad/copy weights into zero-padded buffers ----------------
__global__ void pad_copy_kernel(float* __restrict__ dst, const float* __restrict__ src,
                                int sr, int sc, int dr, int dc) {
    int tot = dr * dc;
    for (int i = blockIdx.x * blockDim.x + threadIdx.x; i < tot; i += gridDim.x * blockDim.x) {
        int r = i / dc, c = i % dc;
        dst[i] = (r < sr && c < sc) ? src[r * sc + c] : 0.f;
    }
}

// ---------------- split fp32 weight [sr x sc] -> transposed bf16 hi/lo [Np x Kp] ----------------
__global__ void split_w_kernel(const float* __restrict__ W, int sr, int sc,
                               __nv_bfloat16* __restrict__ oh, __nv_bfloat16* __restrict__ ol,
                               int Np, int Kp) {
    int tot = Np * Kp;
    for (int i = blockIdx.x * blockDim.x + threadIdx.x; i < tot; i += gridDim.x * blockDim.x) {
        int n = i / Kp, k = i % Kp;
        float v = (k < sr && n < sc) ? W[k * sc + n] : 0.f;
        __nv_bfloat16 h = __float2bfloat16(v);
        oh[i] = h;
        ol[i] = __float2bfloat16(v - __bfloat162float(h));
    }
}

// ---------------- fused concat + bf16 split: [feats|out1|out2|out3|0] -> A1h/A1l [M x 512] ----------------
__global__ void hcat_split_kernel(const float* __restrict__ feats) {
    size_t total = (size_t)MTOT * KP;
    for (size_t i = (size_t)blockIdx.x * blockDim.x + threadIdx.x; i < total;
         i += (size_t)gridDim.x * blockDim.x) {
        size_t m = i >> 9;
        int c = (int)(i & 511);
        float v;
        if (c < 5)        v = feats[m * 5 + c];
        else if (c < 69)  v = g_out1[m * 64 + (c - 5)];
        else if (c < 197) v = g_out2[m * 128 + (c - 69)];
        else if (c < 453) v = g_out3[m * 256 + (c - 197)];
        else              v = 0.f;
        __nv_bfloat16 h = __float2bfloat16(v);
        g_A1h[i] = h;
        g_A1l[i] = __float2bfloat16(v - __bfloat162float(h));
    }
}

// ================= bf16x3-split tensor-core GEMM (mma.sync) =================
// out[M][N] = act(A[M][KP] @ B^T[N][KP] + bias), via ah*bh + ah*bl + al*bh.
// CTA tile 128x128, 8 warps (2M x 4N), warp tile 64x32, m16n8k16.
// mode 0: elu + bf16-split out (oh/ol). mode 1: elu + fp32 out (of).
// smem per stage: Ah,Al,Bh,Bl each [128][40] bf16 (80B rows) = 10240B -> 40960B/stage, 2 stages.
#define STG_BYTES 40960
#define ROWB 80

__global__ void __launch_bounds__(256) gemm_mma(
    const __nv_bfloat16* __restrict__ Ah, const __nv_bfloat16* __restrict__ Al,
    const __nv_bfloat16* __restrict__ Bh, const __nv_bfloat16* __restrict__ Bl,
    const float* __restrict__ bias,
    __nv_bfloat16* __restrict__ oh, __nv_bfloat16* __restrict__ ol,
    float* __restrict__ of, int ldo, int mode) {
    extern __shared__ char smem[];
    float* sbias = (float*)(smem + 2 * STG_BYTES);

    const int tid = threadIdx.x;
    const int warp = tid >> 5, lane = tid & 31;
    const size_t m0 = (size_t)blockIdx.x * 128;
    const int n0 = blockIdx.y * 128;
    const uint32_t sb = smem_u32(smem);

    if (tid < 128) sbias[tid] = bias[n0 + tid];

    // ---- async load of one k-chunk (BK=32) into stage st ----
    auto issue = [&](int st, int k0) {
        uint32_t base = sb + st * STG_BYTES;
        #pragma unroll
        for (int i = tid; i < 2048; i += 256) {
            int mat = i >> 9, j = i & 511, r = j >> 2, c = j & 3;
            uint32_t daddr = base + mat * 10240 + r * ROWB + c * 16;
            const __nv_bfloat16* g;
            if (mat == 0)      g = &Ah[(m0 + r) * KP + k0 + c * 8];
            else if (mat == 1) g = &Al[(m0 + r) * KP + k0 + c * 8];
            else if (mat == 2) g = &Bh[(size_t)(n0 + r) * KP + k0 + c * 8];
            else               g = &Bl[(size_t)(n0 + r) * KP + k0 + c * 8];
            cp16(daddr, g);
        }
        CP_COMMIT();
    };

    const int wm = warp & 1, wn = warp >> 1;
    const int mbase = wm * 64, nbase = wn * 32;

    float acc[4][4][4];
    #pragma unroll
    for (int mi = 0; mi < 4; mi++)
        #pragma unroll
        for (int ni = 0; ni < 4; ni++)
            #pragma unroll
            for (int q = 0; q < 4; q++) acc[mi][ni][q] = 0.f;

    const int lr = lane & 7, seg = lane >> 3;
    // A ldmatrix.x4 address pattern
    const int arow = mbase + (seg & 1) * 8 + lr;
    const int acolq = (seg >> 1) * 8;              // element offset within k16
    // B ldmatrix.x2 address pattern (threads 0-15 meaningful)
    const int brow = nbase + lr;
    const int bcolq = (seg & 1) * 8;

    issue(0, 0);

    const int NSTEP = KP / 32;   // 16
    #pragma unroll 1
    for (int s = 0; s < NSTEP; s++) {
        if (s + 1 < NSTEP) { issue((s + 1) & 1, (s + 1) * 32); CP_WAIT(1); }
        else               { CP_WAIT(0); }
        __syncthreads();
        uint32_t base = sb + (s & 1) * STG_BYTES;
        uint32_t bAh = base, bAl = base + 10240, bBh = base + 20480, bBl = base + 30720;

        #pragma unroll
        for (int ks = 0; ks < 2; ks++) {
            int acol = ks * 16 + acolq;
            int bcol = ks * 16 + bcolq;
            uint32_t ah[4][4], al_[4][4], bh[4][2], bl[4][2];
            #pragma unroll
            for (int mi = 0; mi < 4; mi++) {
                uint32_t ad = bAh + (arow + mi * 16) * ROWB + acol * 2;
                LDSM_X4(ah[mi][0], ah[mi][1], ah[mi][2], ah[mi][3], ad);
                uint32_t ad2 = bAl + (arow + mi * 16) * ROWB + acol * 2;
                LDSM_X4(al_[mi][0], al_[mi][1], al_[mi][2], al_[mi][3], ad2);
            }
            #pragma unroll
            for (int ni = 0; ni < 4; ni++) {
                uint32_t bd = bBh + (brow + ni * 8) * ROWB + bcol * 2;
                LDSM_X2(bh[ni][0], bh[ni][1], bd);
                uint32_t bd2 = bBl + (brow + ni * 8) * ROWB + bcol * 2;
                LDSM_X2(bl[ni][0], bl[ni][1], bd2);
            }
            #pragma unroll
            for (int mi = 0; mi < 4; mi++)
                #pragma unroll
                for (int ni = 0; ni < 4; ni++) {
                    MMA16816(acc[mi][ni], ah[mi][0], ah[mi][1], ah[mi][2], ah[mi][3],
                             bh[ni][0], bh[ni][1]);
                    MMA16816(acc[mi][ni], ah[mi][0], ah[mi][1], ah[mi][2], ah[mi][3],
                             bl[ni][0], bl[ni][1]);
                    MMA16816(acc[mi][ni], al_[mi][0], al_[mi][1], al_[mi][2], al_[mi][3],
                             bh[ni][0], bh[ni][1]);
                }
        }
        __syncthreads();
    }

    // ---- epilogue: bias + elu (+ split) ----
    const int gq = lane >> 2, tq = lane & 3;
    #pragma unroll
    for (int mi = 0; mi < 4; mi++) {
        #pragma unroll
        for (int ni = 0; ni < 4; ni++) {
            #pragma unroll
            for (int half = 0; half < 2; half++) {
                size_t m = m0 + mbase + mi * 16 + gq + half * 8;
                int nl = nbase + ni * 8 + tq * 2;
                float v0 = eluf(acc[mi][ni][half * 2 + 0] + sbias[nl + 0]);
                float v1 = eluf(acc[mi][ni][half * 2 + 1] + sbias[nl + 1]);
                size_t o = m * (size_t)ldo + n0 + nl;
                if (mode == 0) {
                    __nv_bfloat162 hv, lv;
                    hv.x = __float2bfloat16(v0);
                    hv.y = __float2bfloat16(v1);
                    lv.x = __float2bfloat16(v0 - __bfloat162float(hv.x));
                    lv.y = __float2bfloat16(v1 - __bfloat162float(hv.y));
                    *(__nv_bfloat162*)&oh[o] = hv;
                    *(__nv_bfloat162*)&ol[o] = lv;
                } else {
                    float2 fv = make_float2(v0, v1);
                    *(float2*)&of[o] = fv;
                }
            }
        }
    }
}

// ---------------- KNN: block per batch, thread per point ----------------
template<int C>
__global__ void __launch_bounds__(128) knn_kernel(const float* __restrict__ x,
                                                  int* __restrict__ out_idx) {
    extern __shared__ float sm[];
    float* sx = sm;            // [128][C]
    float* sn = sm + NN * C;   // [128]
    int b = blockIdx.x, t = threadIdx.x;
    const float* xb = x + (size_t)b * NN * C;
    for (int i = t; i < NN * C; i += 128) sx[i] = xb[i];
    __syncthreads();
    float nrm = 0.f;
    float rx[C];
    #pragma unroll
    for (int c = 0; c < C; c++) { rx[c] = sx[t * C + c]; nrm += rx[c] * rx[c]; }
    sn[t] = nrm;
    __syncthreads();

    float bd0 = 3e38f, bd1 = 3e38f, bd2 = 3e38f, bd3 = 3e38f;
    int   bi0 = 0, bi1 = 0, bi2 = 0, bi3 = 0;
    for (int j = 0; j < NN; j++) {
        float dot = 0.f;
        if (C % 4 == 0) {
            #pragma unroll
            for (int c = 0; c < C; c += 4) {
                float4 v = *reinterpret_cast<const float4*>(&sx[j * C + c]);
                dot += rx[c] * v.x + rx[c+1] * v.y + rx[c+2] * v.z + rx[c+3] * v.w;
            }
        } else {
            #pragma unroll
            for (int c = 0; c < C; c++) dot += rx[c] * sx[j * C + c];
        }
        float d = nrm + sn[j] - 2.f * dot;
        if (j == t) d += 1e9f;
        if (d < bd3) {
            if (d < bd0)      { bd3=bd2;bi3=bi2; bd2=bd1;bi2=bi1; bd1=bd0;bi1=bi0; bd0=d;bi0=j; }
            else if (d < bd1) { bd3=bd2;bi3=bi2; bd2=bd1;bi2=bi1; bd1=d;bi1=j; }
            else if (d < bd2) { bd3=bd2;bi3=bi2; bd2=d;bi2=j; }
            else              { bd3=d;bi3=j; }
        }
    }
    int* o = out_idx + ((size_t)b * NN + t) * KK;
    o[0] = bi0; o[1] = bi1; o[2] = bi2; o[3] = bi3;
}

// ---------------- EdgeConv stage 1: U = X@W1b ; V = X@W1a - U + b1 ----------------
template<int C, int H>
__global__ void __launch_bounds__(256) stage1_kernel(const float* __restrict__ x,
                                                     const float* __restrict__ w1,
                                                     const float* __restrict__ b1,
                                                     float* __restrict__ U,
                                                     float* __restrict__ V) {
    const int XS = 132;
    extern __shared__ float sm[];
    float* XT = sm;                  // [C][132]
    float* Ba = sm + C * XS;         // [16][64]
    float* Bb = Ba + 16 * 64;        // [16][64]
    int b = blockIdx.x;
    int tid = threadIdx.x;
    int tx = tid & 15, ty = tid >> 4;
    const float* xb = x + (size_t)b * NN * C;
    for (int i = tid; i < NN * C; i += 256) {
        int p = i / C, c = i % C;
        XT[c * XS + p] = xb[i];
    }
    __syncthreads();

    const int NBT = (H + 63) / 64;
    for (int nb = 0; nb < NBT; nb++) {
        float au[8][4], aw[8][4];
        #pragma unroll
        for (int r = 0; r < 8; r++)
            #pragma unroll
            for (int c = 0; c < 4; c++) { au[r][c] = 0.f; aw[r][c] = 0.f; }

        for (int c0 = 0; c0 < C; c0 += 16) {
            int kc = (C - c0 < 16) ? (C - c0) : 16;
            __syncthreads();
            for (int li = tid; li < 16 * 64; li += 256) {
                int kk = li >> 6, n = li & 63;
                int h = nb * 64 + n;
                float va = 0.f, vb = 0.f;
                if (kk < kc && h < H) {
                    va = w1[(size_t)(c0 + kk) * H + h];
                    vb = w1[(size_t)(C + c0 + kk) * H + h];
                }
                Ba[kk * 64 + n] = va;
                Bb[kk * 64 + n] = vb;
            }
            __syncthreads();
            for (int kk = 0; kk < kc; kk++) {
                float4 a0 = *reinterpret_cast<float4*>(&XT[(c0 + kk) * XS + ty * 8]);
                float4 a1 = *reinterpret_cast<float4*>(&XT[(c0 + kk) * XS + ty * 8 + 4]);
                float4 va = *reinterpret_cast<float4*>(&Ba[kk * 64 + tx * 4]);
                float4 vb = *reinterpret_cast<float4*>(&Bb[kk * 64 + tx * 4]);
                float a[8]  = {a0.x, a0.y, a0.z, a0.w, a1.x, a1.y, a1.z, a1.w};
                float wa[4] = {va.x, va.y, va.z, va.w};
                float wb[4] = {vb.x, vb.y, vb.z, vb.w};
                #pragma unroll
                for (int r = 0; r < 8; r++)
                    #pragma unroll
                    for (int c = 0; c < 4; c++) {
                        au[r][c] = fmaf(a[r], wb[c], au[r][c]);
                        aw[r][c] = fmaf(a[r], wa[c], aw[r][c]);
                    }
            }
        }
        #pragma unroll
        for (int r = 0; r < 8; r++) {
            int p = ty * 8 + r;
            size_t base = ((size_t)b * NN + p) * H;
            #pragma unroll
            for (int c = 0; c < 4; c++) {
                int h = nb * 64 + tx * 4 + c;
                if (h < H) {
                    float u = au[r][c];
                    U[base + h] = u;
                    V[base + h] = aw[r][c] - u + b1[h];
                }
            }
        }
    }
}

// ---------------- EdgeConv stage 2: out[p] = mean_k elu(elu(V[p]+U[j]) @ W2 + b2) ----------------
template<int H, int COUT>
__global__ void __launch_bounds__(256) stage2_kernel(const float* __restrict__ U,
                                                     const float* __restrict__ V,
                                                     const int* __restrict__ idx,
                                                     const float* __restrict__ w2,
                                                     const float* __restrict__ b2,
                                                     float* __restrict__ out) {
    const int ES = 132;
    extern __shared__ float sm[];
    float* M1 = sm;              // [H][132]
    float* Bs = sm + H * ES;     // [16][64]
    int b = blockIdx.x, pt = blockIdx.y;
    int tid = threadIdx.x;
    int tx = tid & 15, ty = tid >> 4;
    int p0 = pt * 32;

    {
        int e = tid & 127, s = tid >> 7;
        int pl = e >> 2, kk = e & 3;
        int p = p0 + pl;
        int j = idx[((size_t)b * NN + p) * KK + kk];
        const float* vp = V + ((size_t)b * NN + p) * H;
        const float* up = U + ((size_t)b * NN + j) * H;
        int h0 = s * (H / 2), h1 = h0 + H / 2;
        for (int h = h0; h < h1; h++)
            M1[h * ES + e] = eluf(vp[h] + up[h]);
    }
    __syncthreads();

    const int NBT = COUT / 64;
    for (int nb = 0; nb < NBT; nb++) {
        float acc[8][4];
        #pragma unroll
        for (int r = 0; r < 8; r++)
            #pragma unroll
            for (int c = 0; c < 4; c++) acc[r][c] = 0.f;

        for (int k0 = 0; k0 < H; k0 += 16) {
            __syncthreads();
            {
                int kk = tid >> 4, nq = tid & 15;
                *reinterpret_cast<float4*>(&Bs[kk * 64 + nq * 4]) =
                    *reinterpret_cast<const float4*>(&w2[(size_t)(k0 + kk) * COUT + nb * 64 + nq * 4]);
            }
            __syncthreads();
            #pragma unroll
            for (int kk = 0; kk < 16; kk++) {
                float4 a0 = *reinterpret_cast<float4*>(&M1[(k0 + kk) * ES + ty * 8]);
                float4 a1 = *reinterpret_cast<float4*>(&M1[(k0 + kk) * ES + ty * 8 + 4]);
                float4 b4 = *reinterpret_cast<float4*>(&Bs[kk * 64 + tx * 4]);
                float a[8]  = {a0.x, a0.y, a0.z, a0.w, a1.x, a1.y, a1.z, a1.w};
                float wv[4] = {b4.x, b4.y, b4.z, b4.w};
                #pragma unroll
                for (int r = 0; r < 8; r++)
                    #pragma unroll
                    for (int c = 0; c < 4; c++)
                        acc[r][c] = fmaf(a[r], wv[c], acc[r][c]);
            }
        }
        #pragma unroll
        for (int q = 0; q < 2; q++) {
            int p = p0 + ty * 2 + q;
            #pragma unroll
            for (int c = 0; c < 4; c++) {
                int o = nb * 64 + tx * 4 + c;
                float bias = b2[o];
                float s = 0.f;
                #pragma unroll
                for (int r = 0; r < 4; r++) s += eluf(acc[q * 4 + r][c] + bias);
                out[((size_t)b * NN + p) * COUT + o] = 0.25f * s;
            }
        }
    }
}

// ---------------- final tiny GEMM: out[m][0..1] = h2[m] @ W3p + b3 ----------------
__global__ void final_kernel(const float* __restrict__ b3, float* __restrict__ out) {
    int warp = (blockIdx.x * blockDim.x + threadIdx.x) >> 5;
    int lane = threadIdx.x & 31;
    if (warp >= MTOT) return;
    const float* row = g_h2 + (size_t)warp * 256;
    float a0 = 0.f, a1 = 0.f;
    for (int k = lane; k < 256; k += 32) {
        float v = row[k];
        a0 = fmaf(v, g_W3p[k * 2 + 0], a0);
        a1 = fmaf(v, g_W3p[k * 2 + 1], a1);
    }
    #pragma unroll
    for (int off = 16; off; off >>= 1) {
        a0 += __shfl_down_sync(0xFFFFFFFFu, a0, off);
        a1 += __shfl_down_sync(0xFFFFFFFFu, a1, off);
    }
    if (lane == 0) {
        out[(size_t)warp * 2 + 0] = a0 + b3[0];
        out[(size_t)warp * 2 + 1] = a1 + b3[1];
    }
}

// ---------------- launch ----------------
extern "C" void kernel_launch(void* const* d_in, const int* in_sizes, int n_in,
                              void* d_out, int out_size) {
    const float* coords = (const float*)d_in[0];
    const float* feats  = (const float*)d_in[1];
    const float* c1w1 = (const float*)d_in[2];  const float* c1b1 = (const float*)d_in[3];
    const float* c1w2 = (const float*)d_in[4];  const float* c1b2 = (const float*)d_in[5];
    const float* c2w1 = (const float*)d_in[6];  const float* c2b1 = (const float*)d_in[7];
    const float* c2w2 = (const float*)d_in[8];  const float* c2b2 = (const float*)d_in[9];
    const float* c3w1 = (const float*)d_in[10]; const float* c3b1 = (const float*)d_in[11];
    const float* c3w2 = (const float*)d_in[12]; const float* c3b2 = (const float*)d_in[13];
    const float* ow1  = (const float*)d_in[14]; const float* ob1  = (const float*)d_in[15];
    const float* ow2  = (const float*)d_in[16]; const float* ob2  = (const float*)d_in[17];
    const float* ow3  = (const float*)d_in[18]; const float* ob3  = (const float*)d_in[19];
    float* out = (float*)d_out;

    float *out1p, *out2p, *out3p, *Up, *Vp, *h2p, *b1pp, *b2pp, *W3pp;
    __nv_bfloat16 *A1hp, *A1lp, *h1hp, *h1lp, *Bt1hp, *Bt1lp, *Bt2hp, *Bt2lp;
    int* idxp;
    cudaGetSymbolAddress((void**)&out1p, g_out1);
    cudaGetSymbolAddress((void**)&out2p, g_out2);
    cudaGetSymbolAddress((void**)&out3p, g_out3);
    cudaGetSymbolAddress((void**)&Up,    g_U);
    cudaGetSymbolAddress((void**)&Vp,    g_V);
    cudaGetSymbolAddress((void**)&idxp,  g_idx);
    cudaGetSymbolAddress((void**)&h2p,   g_h2);
    cudaGetSymbolAddress((void**)&b1pp,  g_b1p);
    cudaGetSymbolAddress((void**)&b2pp,  g_b2p);
    cudaGetSymbolAddress((void**)&W3pp,  g_W3p);
    cudaGetSymbolAddress((void**)&A1hp,  g_A1h);
    cudaGetSymbolAddress((void**)&A1lp,  g_A1l);
    cudaGetSymbolAddress((void**)&h1hp,  g_h1h);
    cudaGetSymbolAddress((void**)&h1lp,  g_h1l);
    cudaGetSymbolAddress((void**)&Bt1hp, g_Bt1h);
    cudaGetSymbolAddress((void**)&Bt1lp, g_Bt1l);
    cudaGetSymbolAddress((void**)&Bt2hp, g_Bt2h);
    cudaGetSymbolAddress((void**)&Bt2lp, g_Bt2l);

    const int sm_knn2   = (NN * 2 + NN) * 4;
    const int sm_knn64  = (NN * 64 + NN) * 4;
    const int sm_knn128 = (NN * 128 + NN) * 4;
    const int sm_s1_a = (5 * 132 + 2 * 16 * 64) * 4;
    const int sm_s1_b = (64 * 132 + 2 * 16 * 64) * 4;
    const int sm_s1_c = (128 * 132 + 2 * 16 * 64) * 4;
    const int sm_s2_a = (32 * 132 + 16 * 64) * 4;
    const int sm_s2_b = (96 * 132 + 16 * 64) * 4;
    const int sm_s2_c = (192 * 132 + 16 * 64) * 4;
    const int sm_gemm = 2 * STG_BYTES + 512;   // 82432

    cudaFuncSetAttribute(knn_kernel<128>,          cudaFuncAttributeMaxDynamicSharedMemorySize, sm_knn128);
    cudaFuncSetAttribute(stage1_kernel<128, 192>,  cudaFuncAttributeMaxDynamicSharedMemorySize, sm_s1_c);
    cudaFuncSetAttribute(stage2_kernel<96, 128>,   cudaFuncAttributeMaxDynamicSharedMemorySize, sm_s2_b);
    cudaFuncSetAttribute(stage2_kernel<192, 256>,  cudaFuncAttributeMaxDynamicSharedMemorySize, sm_s2_c);
    cudaFuncSetAttribute(gemm_mma,                 cudaFuncAttributeMaxDynamicSharedMemorySize, sm_gemm);

    // weight prep
    pad_copy_kernel<<<2, 256>>>(b1pp, ob1, 1, 453, 1, 512);
    pad_copy_kernel<<<1, 256>>>(b2pp, ob2, 1, 226, 1, 256);
    pad_copy_kernel<<<2, 256>>>(W3pp, ow3, 226, 2, 256, 2);
    split_w_kernel<<<256, 256>>>(ow1, 453, 453, Bt1hp, Bt1lp, 512, KP);
    split_w_kernel<<<128, 256>>>(ow2, 453, 226, Bt2hp, Bt2lp, 256, KP);

    // edgeconv 1
    knn_kernel<2><<<BB, 128, sm_knn2>>>(coords, idxp);
    stage1_kernel<5, 32><<<BB, 256, sm_s1_a>>>(feats, c1w1, c1b1, Up, Vp);
    stage2_kernel<32, 64><<<dim3(BB, 4), 256, sm_s2_a>>>(Up, Vp, idxp, c1w2, c1b2, out1p);
    // edgeconv 2
    knn_kernel<64><<<BB, 128, sm_knn64>>>(out1p, idxp);
    stage1_kernel<64, 96><<<BB, 256, sm_s1_b>>>(out1p, c2w1, c2b1, Up, Vp);
    stage2_kernel<96, 128><<<dim3(BB, 4), 256, sm_s2_b>>>(Up, Vp, idxp, c2w2, c2b2, out2p);
    // edgeconv 3
    knn_kernel<128><<<BB, 128, sm_knn128>>>(out2p, idxp);
    stage1_kernel<128, 192><<<BB, 256, sm_s1_c>>>(out2p, c3w1, c3b1, Up, Vp);
    stage2_kernel<192, 256><<<dim3(BB, 4), 256, sm_s2_c>>>(Up, Vp, idxp, c3w2, c3b2, out3p);

    // head: fused concat+split, then two tensor-core GEMMs, then tiny final GEMM
    hcat_split_kernel<<<8192, 256>>>(feats);
    gemm_mma<<<dim3(MTOT / 128, 4), 256, sm_gemm>>>(A1hp, A1lp, Bt1hp, Bt1lp, b1pp,
                                                    h1hp, h1lp, nullptr, KP, 0);
    gemm_mma<<<dim3(MTOT / 128, 2), 256, sm_gemm>>>(h1hp, h1lp, Bt2hp, Bt2lp, b2pp,
                                                    nullptr, nullptr, h2p, 256, 1);
    final_kernel<<<MTOT / 8, 256>>>(ob3, out);
}

// round 4
// speedup vs baseline: 1.8334x; 1.3987x over previous
#include <cuda_runtime.h>
#include <cuda_bf16.h>
#include <math.h>
#include <stdint.h>

#define BB 1024
#define NN 128
#define KK 4
#define MTOT (BB*NN)     // 131072
#define ME  (MTOT*KK)    // 524288 edges
#define KP 512           // padded K for head GEMMs

// ---------------- scratch (device globals: allocation-free) ----------------
__device__ float g_out1[MTOT*64];
__device__ float g_out2[MTOT*128];
__device__ float g_out3[MTOT*256];
__device__ float g_U[MTOT*96];
__device__ float g_V[MTOT*96];
__device__ float g_UV[(size_t)MTOT*384];     // stage1-ec3 output: [U(192)|V(192)]
__device__ int   g_idx[MTOT*KK];
__device__ float g_h2[(size_t)MTOT*256];
__device__ float g_b1p[512];
__device__ float g_b2p[256];
__device__ float g_W3p[256*2];
__device__ float g_sb1[384];

// bf16 split operands (16B aligned)
__device__ __align__(16) __nv_bfloat16 g_A1h[(size_t)MTOT*KP];
__device__ __align__(16) __nv_bfloat16 g_A1l[(size_t)MTOT*KP];
__device__ __align__(16) __nv_bfloat16 g_h1h[(size_t)MTOT*KP];
__device__ __align__(16) __nv_bfloat16 g_h1l[(size_t)MTOT*KP];
__device__ __align__(16) __nv_bfloat16 g_X2h[(size_t)MTOT*128];
__device__ __align__(16) __nv_bfloat16 g_X2l[(size_t)MTOT*128];
__device__ __align__(16) __nv_bfloat16 g_Eh[(size_t)ME*192];
__device__ __align__(16) __nv_bfloat16 g_El[(size_t)ME*192];
__device__ __align__(16) __nv_bfloat16 g_Bt1h[512*KP];
__device__ __align__(16) __nv_bfloat16 g_Bt1l[512*KP];
__device__ __align__(16) __nv_bfloat16 g_Bt2h[256*KP];
__device__ __align__(16) __nv_bfloat16 g_Bt2l[256*KP];
__device__ __align__(16) __nv_bfloat16 g_Bc2h[128*96];
__device__ __align__(16) __nv_bfloat16 g_Bc2l[128*96];
__device__ __align__(16) __nv_bfloat16 g_Bc3h[256*192];
__device__ __align__(16) __nv_bfloat16 g_Bc3l[256*192];
__device__ __align__(16) __nv_bfloat16 g_Bs1h[384*128];
__device__ __align__(16) __nv_bfloat16 g_Bs1l[384*128];

__device__ __forceinline__ float eluf(float x) { return x > 0.f ? x : expm1f(x); }

__device__ __forceinline__ uint32_t smem_u32(const void* p) {
    uint32_t a;
    asm("{ .reg .u64 t; cvta.to.shared.u64 t, %1; cvt.u32.u64 %0, t; }" : "=r"(a) : "l"(p));
    return a;
}
__device__ __forceinline__ void cp16(uint32_t dst, const void* src) {
    asm volatile("cp.async.cg.shared.global [%0], [%1], 16;" :: "r"(dst), "l"(src));
}
#define CP_COMMIT() asm volatile("cp.async.commit_group;" ::: "memory")
#define CP_WAIT(n)  asm volatile("cp.async.wait_group %0;" :: "n"(n) : "memory")

#define LDSM_X4(r0, r1, r2, r3, addr) \
    asm volatile("ldmatrix.sync.aligned.m8n8.x4.shared.b16 {%0,%1,%2,%3}, [%4];" \
        : "=r"(r0), "=r"(r1), "=r"(r2), "=r"(r3) : "r"(addr))
#define LDSM_X2(r0, r1, addr) \
    asm volatile("ldmatrix.sync.aligned.m8n8.x2.shared.b16 {%0,%1}, [%2];" \
        : "=r"(r0), "=r"(r1) : "r"(addr))

#define MMA16816(d, a0, a1, a2, a3, b0, b1) \
    asm volatile("mma.sync.aligned.m16n8k16.row.col.f32.bf16.bf16.f32 " \
        "{%0,%1,%2,%3}, {%4,%5,%6,%7}, {%8,%9}, {%0,%1,%2,%3};" \
        : "+f"((d)[0]), "+f"((d)[1]), "+f"((d)[2]), "+f"((d)[3]) \
        : "r"(a0), "r"(a1), "r"(a2), "r"(a3), "r"(b0), "r"(b1))

// ---------------- weight prep kernels ----------------
__global__ void pad_copy_kernel(float* __restrict__ dst, const float* __restrict__ src,
                                int sr, int sc, int dr, int dc) {
    int tot = dr * dc;
    for (int i = blockIdx.x * blockDim.x + threadIdx.x; i < tot; i += gridDim.x * blockDim.x) {
        int r = i / dc, c = i % dc;
        dst[i] = (r < sr && c < sc) ? src[r * sc + c] : 0.f;
    }
}

// split fp32 weight [sr x sc] -> transposed bf16 hi/lo [Np x Kp]
__global__ void split_w_kernel(const float* __restrict__ W, int sr, int sc,
                               __nv_bfloat16* __restrict__ oh, __nv_bfloat16* __restrict__ ol,
                               int Np, int Kp) {
    int tot = Np * Kp;
    for (int i = blockIdx.x * blockDim.x + threadIdx.x; i < tot; i += gridDim.x * blockDim.x) {
        int n = i / Kp, k = i % Kp;
        float v = (k < sr && n < sc) ? W[k * sc + n] : 0.f;
        __nv_bfloat16 h = __float2bfloat16(v);
        oh[i] = h;
        ol[i] = __float2bfloat16(v - __bfloat162float(h));
    }
}

// stage1-ec3 combined weight: rows 0..191 = W1b^T, rows 192..383 = (W1a - W1b)^T; bias [0|b1]
// w1: [256][192] (C=128, H=192)
__global__ void split_s1w_kernel(const float* __restrict__ w1, const float* __restrict__ b1,
                                 __nv_bfloat16* __restrict__ oh, __nv_bfloat16* __restrict__ ol,
                                 float* __restrict__ biasv) {
    int tot = 384 * 128;
    int t0 = blockIdx.x * blockDim.x + threadIdx.x;
    for (int i = t0; i < tot; i += gridDim.x * blockDim.x) {
        int n = i >> 7, k = i & 127;
        float v;
        if (n < 192) v = w1[(size_t)(128 + k) * 192 + n];
        else         v = w1[(size_t)k * 192 + (n - 192)] - w1[(size_t)(128 + k) * 192 + (n - 192)];
        __nv_bfloat16 h = __float2bfloat16(v);
        oh[i] = h;
        ol[i] = __float2bfloat16(v - __bfloat162float(h));
    }
    if (t0 < 384) biasv[t0] = (t0 < 192) ? 0.f : b1[t0 - 192];
}

// ---------------- fused concat + bf16 split -> A1h/A1l [M x 512] ----------------
__global__ void hcat_split_kernel(const float* __restrict__ feats) {
    size_t total = (size_t)MTOT * KP;
    for (size_t i = (size_t)blockIdx.x * blockDim.x + threadIdx.x; i < total;
         i += (size_t)gridDim.x * blockDim.x) {
        size_t m = i >> 9;
        int c = (int)(i & 511);
        float v;
        if (c < 5)        v = feats[m * 5 + c];
        else if (c < 69)  v = g_out1[m * 64 + (c - 5)];
        else if (c < 197) v = g_out2[m * 128 + (c - 69)];
        else if (c < 453) v = g_out3[m * 256 + (c - 197)];
        else              v = 0.f;
        __nv_bfloat16 h = __float2bfloat16(v);
        g_A1h[i] = h;
        g_A1l[i] = __float2bfloat16(v - __bfloat162float(h));
    }
}

// ---------------- edge gather: E[e][c] = elu(V[p][c] + U[j][c]) -> bf16 split ----------------
template<int H>
__global__ void edge_gather(const float* __restrict__ Ub, const float* __restrict__ Vb,
                            int suv, const int* __restrict__ idx,
                            __nv_bfloat16* __restrict__ Eh, __nv_bfloat16* __restrict__ El) {
    const int GP = H / 8;
    size_t total = (size_t)ME * GP;
    for (size_t i = (size_t)blockIdx.x * blockDim.x + threadIdx.x; i < total;
         i += (size_t)gridDim.x * blockDim.x) {
        size_t e = i / GP;
        int g = (int)(i - e * GP);
        int p = (int)(e >> 2);
        int j = idx[e];
        int jg = (p & ~127) + j;     // same batch base
        const float4* vp = (const float4*)(Vb + (size_t)p * suv + g * 8);
        const float4* up = (const float4*)(Ub + (size_t)jg * suv + g * 8);
        float4 v0 = vp[0], v1 = vp[1], u0 = up[0], u1 = up[1];
        float r[8] = {v0.x+u0.x, v0.y+u0.y, v0.z+u0.z, v0.w+u0.w,
                      v1.x+u1.x, v1.y+u1.y, v1.z+u1.z, v1.w+u1.w};
        __nv_bfloat16 hh[8], ll[8];
        #pragma unroll
        for (int q = 0; q < 8; q++) {
            float vv = eluf(r[q]);
            hh[q] = __float2bfloat16(vv);
            ll[q] = __float2bfloat16(vv - __bfloat162float(hh[q]));
        }
        *(uint4*)&Eh[e * H + g * 8] = *(uint4*)hh;
        *(uint4*)&El[e * H + g * 8] = *(uint4*)ll;
    }
}

// ================= bf16x3-split tensor-core GEMM (mma.sync) =================
// out[M][N] = post(A[M][Kdim] @ B^T[N][Kdim] + bias), via ah*bh + ah*bl + al*bh.
// CTA tile 128x128, 8 warps (2M x 4N), warp tile 64x32, m16n8k16, cp.async double buffer.
// mode 0: elu + bf16-split (oh/ol). mode 1: elu + fp32 (of). mode 3: plain fp32 (of).
// mode 2: per-edge elu then mean over 4 consecutive rows -> fp32 of (+ optional split oh/ol).
#define STG_BYTES 40960
#define ROWB 80

__global__ void __launch_bounds__(256) gemm_mma(
    const __nv_bfloat16* __restrict__ Ah, const __nv_bfloat16* __restrict__ Al,
    const __nv_bfloat16* __restrict__ Bh, const __nv_bfloat16* __restrict__ Bl,
    const float* __restrict__ bias,
    __nv_bfloat16* __restrict__ oh, __nv_bfloat16* __restrict__ ol,
    float* __restrict__ of, int ldo, int Kdim, int mode) {
    extern __shared__ char smem[];
    float* sbias = (float*)(smem + 2 * STG_BYTES);

    const int tid = threadIdx.x;
    const int warp = tid >> 5, lane = tid & 31;
    const size_t m0 = (size_t)blockIdx.x * 128;
    const int n0 = blockIdx.y * 128;
    const uint32_t sb = smem_u32(smem);

    if (tid < 128) sbias[tid] = bias[n0 + tid];

    auto issue = [&](int st, int k0) {
        uint32_t base = sb + st * STG_BYTES;
        #pragma unroll
        for (int i = tid; i < 2048; i += 256) {
            int mat = i >> 9, j = i & 511, r = j >> 2, c = j & 3;
            uint32_t daddr = base + mat * 10240 + r * ROWB + c * 16;
            const __nv_bfloat16* g;
            if (mat == 0)      g = &Ah[(m0 + r) * Kdim + k0 + c * 8];
            else if (mat == 1) g = &Al[(m0 + r) * Kdim + k0 + c * 8];
            else if (mat == 2) g = &Bh[(size_t)(n0 + r) * Kdim + k0 + c * 8];
            else               g = &Bl[(size_t)(n0 + r) * Kdim + k0 + c * 8];
            cp16(daddr, g);
        }
        CP_COMMIT();
    };

    const int wm = warp & 1, wn = warp >> 1;
    const int mbase = wm * 64, nbase = wn * 32;

    float acc[4][4][4];
    #pragma unroll
    for (int mi = 0; mi < 4; mi++)
        #pragma unroll
        for (int ni = 0; ni < 4; ni++)
            #pragma unroll
            for (int q = 0; q < 4; q++) acc[mi][ni][q] = 0.f;

    const int lr = lane & 7, seg = lane >> 3;
    const int arow = mbase + (seg & 1) * 8 + lr;
    const int acolq = (seg >> 1) * 8;
    const int brow = nbase + lr;
    const int bcolq = (seg & 1) * 8;

    issue(0, 0);

    const int NSTEP = Kdim >> 5;
    #pragma unroll 1
    for (int s = 0; s < NSTEP; s++) {
        if (s + 1 < NSTEP) { issue((s + 1) & 1, (s + 1) * 32); CP_WAIT(1); }
        else               { CP_WAIT(0); }
        __syncthreads();
        uint32_t base = sb + (s & 1) * STG_BYTES;
        uint32_t bAh = base, bAl = base + 10240, bBh = base + 20480, bBl = base + 30720;

        #pragma unroll
        for (int ks = 0; ks < 2; ks++) {
            int acol = ks * 16 + acolq;
            int bcol = ks * 16 + bcolq;
            uint32_t ah[4][4], al_[4][4], bh[4][2], bl[4][2];
            #pragma unroll
            for (int mi = 0; mi < 4; mi++) {
                LDSM_X4(ah[mi][0], ah[mi][1], ah[mi][2], ah[mi][3],
                        bAh + (arow + mi * 16) * ROWB + acol * 2);
                LDSM_X4(al_[mi][0], al_[mi][1], al_[mi][2], al_[mi][3],
                        bAl + (arow + mi * 16) * ROWB + acol * 2);
            }
            #pragma unroll
            for (int ni = 0; ni < 4; ni++) {
                LDSM_X2(bh[ni][0], bh[ni][1], bBh + (brow + ni * 8) * ROWB + bcol * 2);
                LDSM_X2(bl[ni][0], bl[ni][1], bBl + (brow + ni * 8) * ROWB + bcol * 2);
            }
            #pragma unroll
            for (int mi = 0; mi < 4; mi++)
                #pragma unroll
                for (int ni = 0; ni < 4; ni++) {
                    MMA16816(acc[mi][ni], ah[mi][0], ah[mi][1], ah[mi][2], ah[mi][3],
                             bh[ni][0], bh[ni][1]);
                    MMA16816(acc[mi][ni], ah[mi][0], ah[mi][1], ah[mi][2], ah[mi][3],
                             bl[ni][0], bl[ni][1]);
                    MMA16816(acc[mi][ni], al_[mi][0], al_[mi][1], al_[mi][2], al_[mi][3],
                             bh[ni][0], bh[ni][1]);
                }
        }
        __syncthreads();
    }

    const int gq = lane >> 2, tq = lane & 3;

    if (mode == 2) {
        // stage elu(acc+bias) for 128 edge rows, then mean over groups of 4 rows
        float* stg = (float*)smem;
        #pragma unroll
        for (int mi = 0; mi < 4; mi++)
            #pragma unroll
            for (int ni = 0; ni < 4; ni++)
                #pragma unroll
                for (int half = 0; half < 2; half++) {
                    int ml = mbase + mi * 16 + gq + half * 8;
                    int nl = nbase + ni * 8 + tq * 2;
                    stg[ml * 132 + nl]     = eluf(acc[mi][ni][half * 2 + 0] + sbias[nl]);
                    stg[ml * 132 + nl + 1] = eluf(acc[mi][ni][half * 2 + 1] + sbias[nl + 1]);
                }
        __syncthreads();
        for (int i = tid; i < 32 * 128; i += 256) {
            int pl = i >> 7, c = i & 127;
            float s4 = stg[(pl * 4 + 0) * 132 + c] + stg[(pl * 4 + 1) * 132 + c]
                     + stg[(pl * 4 + 2) * 132 + c] + stg[(pl * 4 + 3) * 132 + c];
            float v = 0.25f * s4;
            size_t pm = (m0 >> 2) + pl;
            size_t o = pm * (size_t)ldo + n0 + c;
            of[o] = v;
            if (oh) {
                __nv_bfloat16 h = __float2bfloat16(v);
                oh[o] = h;
                ol[o] = __float2bfloat16(v - __bfloat162float(h));
            }
        }
        return;
    }

    const bool doelu = (mode != 3);
    #pragma unroll
    for (int mi = 0; mi < 4; mi++) {
        #pragma unroll
        for (int ni = 0; ni < 4; ni++) {
            #pragma unroll
            for (int half = 0; half < 2; half++) {
                size_t m = m0 + mbase + mi * 16 + gq + half * 8;
                int nl = nbase + ni * 8 + tq * 2;
                float v0 = acc[mi][ni][half * 2 + 0] + sbias[nl];
                float v1 = acc[mi][ni][half * 2 + 1] + sbias[nl + 1];
                if (doelu) { v0 = eluf(v0); v1 = eluf(v1); }
                size_t o = m * (size_t)ldo + n0 + nl;
                if (mode == 0) {
                    __nv_bfloat162 hv, lv;
                    hv.x = __float2bfloat16(v0);
                    hv.y = __float2bfloat16(v1);
                    lv.x = __float2bfloat16(v0 - __bfloat162float(hv.x));
                    lv.y = __float2bfloat16(v1 - __bfloat162float(hv.y));
                    *(__nv_bfloat162*)&oh[o] = hv;
                    *(__nv_bfloat162*)&ol[o] = lv;
                } else {
                    *(float2*)&of[o] = make_float2(v0, v1);
                }
            }
        }
    }
}

// ---------------- KNN: block per batch, thread per point ----------------
template<int C>
__global__ void __launch_bounds__(128) knn_kernel(const float* __restrict__ x,
                                                  int* __restrict__ out_idx) {
    extern __shared__ float sm[];
    float* sx = sm;
    float* sn = sm + NN * C;
    int b = blockIdx.x, t = threadIdx.x;
    const float* xb = x + (size_t)b * NN * C;
    for (int i = t; i < NN * C; i += 128) sx[i] = xb[i];
    __syncthreads();
    float nrm = 0.f;
    float rx[C];
    #pragma unroll
    for (int c = 0; c < C; c++) { rx[c] = sx[t * C + c]; nrm += rx[c] * rx[c]; }
    sn[t] = nrm;
    __syncthreads();

    float bd0 = 3e38f, bd1 = 3e38f, bd2 = 3e38f, bd3 = 3e38f;
    int   bi0 = 0, bi1 = 0, bi2 = 0, bi3 = 0;
    for (int j = 0; j < NN; j++) {
        float dot = 0.f;
        if (C % 4 == 0) {
            #pragma unroll
            for (int c = 0; c < C; c += 4) {
                float4 v = *reinterpret_cast<const float4*>(&sx[j * C + c]);
                dot += rx[c] * v.x + rx[c+1] * v.y + rx[c+2] * v.z + rx[c+3] * v.w;
            }
        } else {
            #pragma unroll
            for (int c = 0; c < C; c++) dot += rx[c] * sx[j * C + c];
        }
        float d = nrm + sn[j] - 2.f * dot;
        if (j == t) d += 1e9f;
        if (d < bd3) {
            if (d < bd0)      { bd3=bd2;bi3=bi2; bd2=bd1;bi2=bi1; bd1=bd0;bi1=bi0; bd0=d;bi0=j; }
            else if (d < bd1) { bd3=bd2;bi3=bi2; bd2=bd1;bi2=bi1; bd1=d;bi1=j; }
            else if (d < bd2) { bd3=bd2;bi3=bi2; bd2=d;bi2=j; }
            else              { bd3=d;bi3=j; }
        }
    }
    int* o = out_idx + ((size_t)b * NN + t) * KK;
    o[0] = bi0; o[1] = bi1; o[2] = bi2; o[3] = bi3;
}

// ---------------- EdgeConv stage 1 (fp32, small stages): U = X@W1b ; V = X@W1a - U + b1 ----------------
template<int C, int H>
__global__ void __launch_bounds__(256) stage1_kernel(const float* __restrict__ x,
                                                     const float* __restrict__ w1,
                                                     const float* __restrict__ b1,
                                                     float* __restrict__ U,
                                                     float* __restrict__ V) {
    const int XS = 132;
    extern __shared__ float sm[];
    float* XT = sm;
    float* Ba = sm + C * XS;
    float* Bb = Ba + 16 * 64;
    int b = blockIdx.x;
    int tid = threadIdx.x;
    int tx = tid & 15, ty = tid >> 4;
    const float* xb = x + (size_t)b * NN * C;
    for (int i = tid; i < NN * C; i += 256) {
        int p = i / C, c = i % C;
        XT[c * XS + p] = xb[i];
    }
    __syncthreads();

    const int NBT = (H + 63) / 64;
    for (int nb = 0; nb < NBT; nb++) {
        float au[8][4], aw[8][4];
        #pragma unroll
        for (int r = 0; r < 8; r++)
            #pragma unroll
            for (int c = 0; c < 4; c++) { au[r][c] = 0.f; aw[r][c] = 0.f; }

        for (int c0 = 0; c0 < C; c0 += 16) {
            int kc = (C - c0 < 16) ? (C - c0) : 16;
            __syncthreads();
            for (int li = tid; li < 16 * 64; li += 256) {
                int kk = li >> 6, n = li & 63;
                int h = nb * 64 + n;
                float va = 0.f, vb = 0.f;
                if (kk < kc && h < H) {
                    va = w1[(size_t)(c0 + kk) * H + h];
                    vb = w1[(size_t)(C + c0 + kk) * H + h];
                }
                Ba[kk * 64 + n] = va;
                Bb[kk * 64 + n] = vb;
            }
            __syncthreads();
            for (int kk = 0; kk < kc; kk++) {
                float4 a0 = *reinterpret_cast<float4*>(&XT[(c0 + kk) * XS + ty * 8]);
                float4 a1 = *reinterpret_cast<float4*>(&XT[(c0 + kk) * XS + ty * 8 + 4]);
                float4 va = *reinterpret_cast<float4*>(&Ba[kk * 64 + tx * 4]);
                float4 vb = *reinterpret_cast<float4*>(&Bb[kk * 64 + tx * 4]);
                float a[8]  = {a0.x, a0.y, a0.z, a0.w, a1.x, a1.y, a1.z, a1.w};
                float wa[4] = {va.x, va.y, va.z, va.w};
                float wb[4] = {vb.x, vb.y, vb.z, vb.w};
                #pragma unroll
                for (int r = 0; r < 8; r++)
                    #pragma unroll
                    for (int c = 0; c < 4; c++) {
                        au[r][c] = fmaf(a[r], wb[c], au[r][c]);
                        aw[r][c] = fmaf(a[r], wa[c], aw[r][c]);
                    }
            }
        }
        #pragma unroll
        for (int r = 0; r < 8; r++) {
            int p = ty * 8 + r;
            size_t base = ((size_t)b * NN + p) * H;
            #pragma unroll
            for (int c = 0; c < 4; c++) {
                int h = nb * 64 + tx * 4 + c;
                if (h < H) {
                    float u = au[r][c];
                    U[base + h] = u;
                    V[base + h] = aw[r][c] - u + b1[h];
                }
            }
        }
    }
}

// ---------------- EdgeConv stage 2 fp32 (only ec1) ----------------
template<int H, int COUT>
__global__ void __launch_bounds__(256) stage2_kernel(const float* __restrict__ U,
                                                     const float* __restrict__ V,
                                                     const int* __restrict__ idx,
                                                     const float* __restrict__ w2,
                                                     const float* __restrict__ b2,
                                                     float* __restrict__ out) {
    const int ES = 132;
    extern __shared__ float sm[];
    float* M1 = sm;
    float* Bs = sm + H * ES;
    int b = blockIdx.x, pt = blockIdx.y;
    int tid = threadIdx.x;
    int tx = tid & 15, ty = tid >> 4;
    int p0 = pt * 32;

    {
        int e = tid & 127, s = tid >> 7;
        int pl = e >> 2, kk = e & 3;
        int p = p0 + pl;
        int j = idx[((size_t)b * NN + p) * KK + kk];
        const float* vp = V + ((size_t)b * NN + p) * H;
        const float* up = U + ((size_t)b * NN + j) * H;
        int h0 = s * (H / 2), h1 = h0 + H / 2;
        for (int h = h0; h < h1; h++)
            M1[h * ES + e] = eluf(vp[h] + up[h]);
    }
    __syncthreads();

    const int NBT = COUT / 64;
    for (int nb = 0; nb < NBT; nb++) {
        float acc[8][4];
        #pragma unroll
        for (int r = 0; r < 8; r++)
            #pragma unroll
            for (int c = 0; c < 4; c++) acc[r][c] = 0.f;

        for (int k0 = 0; k0 < H; k0 += 16) {
            __syncthreads();
            {
                int kk = tid >> 4, nq = tid & 15;
                *reinterpret_cast<float4*>(&Bs[kk * 64 + nq * 4]) =
                    *reinterpret_cast<const float4*>(&w2[(size_t)(k0 + kk) * COUT + nb * 64 + nq * 4]);
            }
            __syncthreads();
            #pragma unroll
            for (int kk = 0; kk < 16; kk++) {
                float4 a0 = *reinterpret_cast<float4*>(&M1[(k0 + kk) * ES + ty * 8]);
                float4 a1 = *reinterpret_cast<float4*>(&M1[(k0 + kk) * ES + ty * 8 + 4]);
                float4 b4 = *reinterpret_cast<float4*>(&Bs[kk * 64 + tx * 4]);
                float a[8]  = {a0.x, a0.y, a0.z, a0.w, a1.x, a1.y, a1.z, a1.w};
                float wv[4] = {b4.x, b4.y, b4.z, b4.w};
                #pragma unroll
                for (int r = 0; r < 8; r++)
                    #pragma unroll
                    for (int c = 0; c < 4; c++)
                        acc[r][c] = fmaf(a[r], wv[c], acc[r][c]);
            }
        }
        #pragma unroll
        for (int q = 0; q < 2; q++) {
            int p = p0 + ty * 2 + q;
            #pragma unroll
            for (int c = 0; c < 4; c++) {
                int o = nb * 64 + tx * 4 + c;
                float bias = b2[o];
                float s = 0.f;
                #pragma unroll
                for (int r = 0; r < 4; r++) s += eluf(acc[q * 4 + r][c] + bias);
                out[((size_t)b * NN + p) * COUT + o] = 0.25f * s;
            }
        }
    }
}

// ---------------- final tiny GEMM ----------------
__global__ void final_kernel(const float* __restrict__ b3, float* __restrict__ out) {
    int warp = (blockIdx.x * blockDim.x + threadIdx.x) >> 5;
    int lane = threadIdx.x & 31;
    if (warp >= MTOT) return;
    const float* row = g_h2 + (size_t)warp * 256;
    float a0 = 0.f, a1 = 0.f;
    for (int k = lane; k < 256; k += 32) {
        float v = row[k];
        a0 = fmaf(v, g_W3p[k * 2 + 0], a0);
        a1 = fmaf(v, g_W3p[k * 2 + 1], a1);
    }
    #pragma unroll
    for (int off = 16; off; off >>= 1) {
        a0 += __shfl_down_sync(0xFFFFFFFFu, a0, off);
        a1 += __shfl_down_sync(0xFFFFFFFFu, a1, off);
    }
    if (lane == 0) {
        out[(size_t)warp * 2 + 0] = a0 + b3[0];
        out[(size_t)warp * 2 + 1] = a1 + b3[1];
    }
}

// ---------------- launch ----------------
extern "C" void kernel_launch(void* const* d_in, const int* in_sizes, int n_in,
                              void* d_out, int out_size) {
    const float* coords = (const float*)d_in[0];
    const float* feats  = (const float*)d_in[1];
    const float* c1w1 = (const float*)d_in[2];  const float* c1b1 = (const float*)d_in[3];
    const float* c1w2 = (const float*)d_in[4];  const float* c1b2 = (const float*)d_in[5];
    const float* c2w1 = (const float*)d_in[6];  const float* c2b1 = (const float*)d_in[7];
    const float* c2w2 = (const float*)d_in[8];  const float* c2b2 = (const float*)d_in[9];
    const float* c3w1 = (const float*)d_in[10]; const float* c3b1 = (const float*)d_in[11];
    const float* c3w2 = (const float*)d_in[12]; const float* c3b2 = (const float*)d_in[13];
    const float* ow1  = (const float*)d_in[14]; const float* ob1  = (const float*)d_in[15];
    const float* ow2  = (const float*)d_in[16]; const float* ob2  = (const float*)d_in[17];
    const float* ow3  = (const float*)d_in[18]; const float* ob3  = (const float*)d_in[19];
    float* out = (float*)d_out;

    float *out1p, *out2p, *out3p, *Up, *Vp, *UVp, *h2p, *b1pp, *b2pp, *W3pp, *sb1p;
    __nv_bfloat16 *A1hp, *A1lp, *h1hp, *h1lp, *X2hp, *X2lp, *Ehp, *Elp;
    __nv_bfloat16 *Bt1hp, *Bt1lp, *Bt2hp, *Bt2lp, *Bc2hp, *Bc2lp, *Bc3hp, *Bc3lp, *Bs1hp, *Bs1lp;
    int* idxp;
    cudaGetSymbolAddress((void**)&out1p, g_out1);
    cudaGetSymbolAddress((void**)&out2p, g_out2);
    cudaGetSymbolAddress((void**)&out3p, g_out3);
    cudaGetSymbolAddress((void**)&Up,    g_U);
    cudaGetSymbolAddress((void**)&Vp,    g_V);
    cudaGetSymbolAddress((void**)&UVp,   g_UV);
    cudaGetSymbolAddress((void**)&idxp,  g_idx);
    cudaGetSymbolAddress((void**)&h2p,   g_h2);
    cudaGetSymbolAddress((void**)&b1pp,  g_b1p);
    cudaGetSymbolAddress((void**)&b2pp,  g_b2p);
    cudaGetSymbolAddress((void**)&W3pp,  g_W3p);
    cudaGetSymbolAddress((void**)&sb1p,  g_sb1);
    cudaGetSymbolAddress((void**)&A1hp,  g_A1h);
    cudaGetSymbolAddress((void**)&A1lp,  g_A1l);
    cudaGetSymbolAddress((void**)&h1hp,  g_h1h);
    cudaGetSymbolAddress((void**)&h1lp,  g_h1l);
    cudaGetSymbolAddress((void**)&X2hp,  g_X2h);
    cudaGetSymbolAddress((void**)&X2lp,  g_X2l);
    cudaGetSymbolAddress((void**)&Ehp,   g_Eh);
    cudaGetSymbolAddress((void**)&Elp,   g_El);
    cudaGetSymbolAddress((void**)&Bt1hp, g_Bt1h);
    cudaGetSymbolAddress((void**)&Bt1lp, g_Bt1l);
    cudaGetSymbolAddress((void**)&Bt2hp, g_Bt2h);
    cudaGetSymbolAddress((void**)&Bt2lp, g_Bt2l);
    cudaGetSymbolAddress((void**)&Bc2hp, g_Bc2h);
    cudaGetSymbolAddress((void**)&Bc2lp, g_Bc2l);
    cudaGetSymbolAddress((void**)&Bc3hp, g_Bc3h);
    cudaGetSymbolAddress((void**)&Bc3lp, g_Bc3l);
    cudaGetSymbolAddress((void**)&Bs1hp, g_Bs1h);
    cudaGetSymbolAddress((void**)&Bs1lp, g_Bs1l);

    const int sm_knn2   = (NN * 2 + NN) * 4;
    const int sm_knn64  = (NN * 64 + NN) * 4;
    const int sm_knn128 = (NN * 128 + NN) * 4;
    const int sm_s1_a = (5 * 132 + 2 * 16 * 64) * 4;
    const int sm_s1_b = (64 * 132 + 2 * 16 * 64) * 4;
    const int sm_s2_a = (32 * 132 + 16 * 64) * 4;
    const int sm_gemm = 2 * STG_BYTES + 512;   // 82432

    cudaFuncSetAttribute(knn_kernel<128>, cudaFuncAttributeMaxDynamicSharedMemorySize, sm_knn128);
    cudaFuncSetAttribute(gemm_mma,        cudaFuncAttributeMaxDynamicSharedMemorySize, sm_gemm);

    // weight prep
    pad_copy_kernel<<<2, 256>>>(b1pp, ob1, 1, 453, 1, 512);
    pad_copy_kernel<<<1, 256>>>(b2pp, ob2, 1, 226, 1, 256);
    pad_copy_kernel<<<2, 256>>>(W3pp, ow3, 226, 2, 256, 2);
    split_w_kernel<<<256, 256>>>(ow1, 453, 453, Bt1hp, Bt1lp, 512, KP);
    split_w_kernel<<<128, 256>>>(ow2, 453, 226, Bt2hp, Bt2lp, 256, KP);
    split_w_kernel<<<16, 256>>>(c2w2, 96, 128, Bc2hp, Bc2lp, 128, 96);
    split_w_kernel<<<48, 256>>>(c3w2, 192, 256, Bc3hp, Bc3lp, 256, 192);
    split_s1w_kernel<<<48, 256>>>(c3w1, c3b1, Bs1hp, Bs1lp, sb1p);

    // ---- edgeconv 1 (fp32: tiny) ----
    knn_kernel<2><<<BB, 128, sm_knn2>>>(coords, idxp);
    stage1_kernel<5, 32><<<BB, 256, sm_s1_a>>>(feats, c1w1, c1b1, Up, Vp);
    stage2_kernel<32, 64><<<dim3(BB, 4), 256, sm_s2_a>>>(Up, Vp, idxp, c1w2, c1b2, out1p);

    // ---- edgeconv 2 ----
    knn_kernel<64><<<BB, 128, sm_knn64>>>(out1p, idxp);
    stage1_kernel<64, 96><<<BB, 256, sm_s1_b>>>(out1p, c2w1, c2b1, Up, Vp);
    edge_gather<96><<<4096, 256>>>(Up, Vp, 96, idxp, Ehp, Elp);
    gemm_mma<<<dim3(ME / 128, 1), 256, sm_gemm>>>(Ehp, Elp, Bc2hp, Bc2lp, c2b2,
                                                  X2hp, X2lp, out2p, 128, 96, 2);

    // ---- edgeconv 3 ----
    knn_kernel<128><<<BB, 128, sm_knn128>>>(out2p, idxp);
    gemm_mma<<<dim3(MTOT / 128, 3), 256, sm_gemm>>>(X2hp, X2lp, Bs1hp, Bs1lp, sb1p,
                                                    nullptr, nullptr, UVp, 384, 128, 3);
    edge_gather<192><<<8192, 256>>>(UVp, UVp + 192, 384, idxp, Ehp, Elp);
    gemm_mma<<<dim3(ME / 128, 2), 256, sm_gemm>>>(Ehp, Elp, Bc3hp, Bc3lp, c3b2,
                                                  nullptr, nullptr, out3p, 256, 192, 2);

    // ---- head ----
    hcat_split_kernel<<<8192, 256>>>(feats);
    gemm_mma<<<dim3(MTOT / 128, 4), 256, sm_gemm>>>(A1hp, A1lp, Bt1hp, Bt1lp, b1pp,
                                                    h1hp, h1lp, nullptr, KP, 512, 0);
    gemm_mma<<<dim3(MTOT / 128, 2), 256, sm_gemm>>>(h1hp, h1lp, Bt2hp, Bt2lp, b2pp,
                                                    nullptr, nullptr, h2p, 256, 512, 1);
    final_kernel<<<MTOT / 8, 256>>>(ob3, out);
}